// round 5
// baseline (speedup 1.0000x reference)
#include <cuda_runtime.h>

// ---------------------------------------------------------------------------
// 3x conv3x3 chain, fp32, NCHW, stride 1 pad 1. N=16, H=W=224, 64->128->128->64.
//
// Round 2: software-pipelined direct conv around packed fp32x2 FMA.
//  - Double-buffered smem (CI_TILE=2 channels per stage, 2 stages, ~39 KB).
//  - Register-staged prefetch: all next-stage LDGs issued BEFORE computing the
//    current stage; STS after barrier. DRAM latency hidden under 1152 cycles
//    of FMA2 work.
//  - Per-slot global offsets (bounds folded in as -1) computed ONCE before the
//    main loop -> no divisions / bounds math in the hot loop.
//  - Dual smem copies (natural + shifted-by-one) keep every 3x3 tap an aligned
//    LDS.64 pixel pair; weights duplicated (w,w) for broadcast LDS.64.
//  - Per thread: 8 co x 4 rows x 2 cols = 64 outputs in 32 packed accumulators.
// ---------------------------------------------------------------------------

#define TILE      32
#define CI_TILE   2
#define HALO      34
#define HALO2     1156
#define NELEM     (CI_TILE * HALO2)       // 2312
#define NSLOT     ((NELEM + 127) / 128)   // 19
#define HW        224
#define HW2       (HW * HW)
#define CO_TILE   8
#define NW        (CO_TILE * CI_TILE * 9) // 144 weight floats per stage

__device__ float g_buf1[102760448];
__device__ float g_buf2[102760448];

typedef unsigned long long u64;

__device__ __forceinline__ void fma2(u64& d, u64 a, u64 b)
{
    // packed 2xfp32 FMA: d.lo += a.lo*b.lo ; d.hi += a.hi*b.hi
    asm("fma.rn.f32x2 %0, %1, %2, %0;" : "+l"(d) : "l"(a), "l"(b));
}

template <int CIN>
__global__ __launch_bounds__(128, 3)
void conv3x3_pipe(const float* __restrict__ in,
                  const float* __restrict__ wgt,
                  float* __restrict__ out,
                  int Cout)
{
    __shared__ __align__(16) float  sA[2][NELEM];   // natural copy
    __shared__ __align__(16) float  sB[2][NELEM];   // shifted: sB[j] = v[j+1]
    __shared__ __align__(16) float2 sW[2][NW];      // duplicated weights

    const int tid = threadIdx.x;
    const int tx  = tid & 15;
    const int ty  = tid >> 4;
    const int cog = blockIdx.x;                  // co-group fastest -> L2 reuse
    const int bh  = blockIdx.y / 7;
    const int bw  = blockIdx.y - bh * 7;
    const int n   = blockIdx.z;
    const int hb  = bh * TILE, wb = bw * TILE;
    const int c0  = 2 * tx;                      // even -> aligned LDS.64
    const int r0  = 4 * ty;

    // ---- per-slot input offsets, computed ONCE (bounds folded in as -1) ----
    int goff[NSLOT];
#pragma unroll
    for (int k = 0; k < NSLOT; k++) {
        int idx = tid + 128 * k;
        int ciL = idx / HALO2;
        int rem = idx - ciL * HALO2;
        int r   = rem / HALO;
        int c   = rem - r * HALO;
        int gh  = hb - 1 + r, gw = wb - 1 + c;
        bool ok = (idx < NELEM) & ((unsigned)gh < HW) & ((unsigned)gw < HW);
        goff[k] = ok ? (ciL * HW2 + gh * HW + gw) : -1;
    }
    const bool tail = tid < (NELEM - 128 * (NSLOT - 1));   // last partial slot
    // sB write index for slot 0: idx==0 redirected to an unused cell
    const int sb0 = (tid == 0) ? (NELEM - 1) : (tid - 1);

    // ---- weight slot offsets (144 floats per stage; 128 + 16 threads) ----
    int wo0, wo1;
    {
        int idx = tid;
        int co = idx / (CI_TILE * 9); int rem = idx - co * (CI_TILE * 9);
        int ciL = rem / 9; int k = rem - ciL * 9;
        wo0 = ((cog * CO_TILE + co) * CIN + ciL) * 9 + k;
        idx = tid + 128;
        co = idx / (CI_TILE * 9); rem = idx - co * (CI_TILE * 9);
        ciL = rem / 9; k = rem - ciL * 9;
        wo1 = ((cog * CO_TILE + co) * CIN + ciL) * 9 + k;
    }
    const bool w2nd = (tid + 128) < NW;

    const float* src = in + (size_t)n * CIN * HW2;

    u64 acc[CO_TILE][4];
#pragma unroll
    for (int co = 0; co < CO_TILE; co++)
#pragma unroll
        for (int r = 0; r < 4; r++) acc[co][r] = 0ull;

    const int NSTAGE = CIN / CI_TILE;

    // ---- prologue: fill stage 0 directly ----
    {
#pragma unroll
        for (int k = 0; k < NSLOT; k++) {
            float v = 0.0f;
            if (goff[k] >= 0) v = __ldg(src + goff[k]);
            int idx = tid + 128 * k;
            if (k < NSLOT - 1 || tail) {
                sA[0][idx] = v;
                sB[0][(k == 0) ? sb0 : (idx - 1)] = v;
            }
        }
        float w0 = __ldg(wgt + wo0);
        sW[0][tid] = make_float2(w0, w0);
        if (w2nd) { float w1 = __ldg(wgt + wo1); sW[0][tid + 128] = make_float2(w1, w1); }
    }
    __syncthreads();

    for (int s = 0; s < NSTAGE; s++) {
        const int  cur  = s & 1;
        const int  nxt  = cur ^ 1;
        const bool more = (s + 1) < NSTAGE;

        // ---- prefetch stage s+1 into registers (latency hidden by compute) ----
        float v[NSLOT];
        float w0 = 0.0f, w1 = 0.0f;
        if (more) {
            const float* p = src + (size_t)(s + 1) * CI_TILE * HW2;
#pragma unroll
            for (int k = 0; k < NSLOT; k++) {
                v[k] = 0.0f;
                if (goff[k] >= 0) v[k] = __ldg(p + goff[k]);
            }
            w0 = __ldg(wgt + wo0 + (s + 1) * CI_TILE * 9);
            if (w2nd) w1 = __ldg(wgt + wo1 + (s + 1) * CI_TILE * 9);
        }

        // ---- compute stage s ----
        const float*  aBase = sA[cur];
        const float*  bBase = sB[cur];
        const float2* wBase = sW[cur];
#pragma unroll 1
        for (int ciL = 0; ciL < CI_TILE; ciL++) {
            u64 inp[6][3];
#pragma unroll
            for (int r = 0; r < 6; r++) {
                const float* pa = aBase + ciL * HALO2 + (r0 + r) * HALO + c0;
                const float* pb = bBase + ciL * HALO2 + (r0 + r) * HALO + c0;
                inp[r][0] = *reinterpret_cast<const u64*>(pa);
                inp[r][1] = *reinterpret_cast<const u64*>(pb);
                inp[r][2] = *reinterpret_cast<const u64*>(pa + 2);
            }
#pragma unroll
            for (int co = 0; co < CO_TILE; co++) {
#pragma unroll
                for (int kh = 0; kh < 3; kh++) {
#pragma unroll
                    for (int kw = 0; kw < 3; kw++) {
                        u64 wp = *reinterpret_cast<const u64*>(
                            &wBase[(co * CI_TILE + ciL) * 9 + kh * 3 + kw]);
#pragma unroll
                        for (int r2 = 0; r2 < 4; r2++)
                            fma2(acc[co][r2], inp[r2 + kh][kw], wp);
                    }
                }
            }
        }
        __syncthreads();   // everyone done reading buf[nxt] (stage s-1)

        // ---- publish stage s+1 ----
        if (more) {
#pragma unroll
            for (int k = 0; k < NSLOT; k++) {
                int idx = tid + 128 * k;
                if (k < NSLOT - 1 || tail) {
                    sA[nxt][idx] = v[k];
                    sB[nxt][(k == 0) ? sb0 : (idx - 1)] = v[k];
                }
            }
            sW[nxt][tid] = make_float2(w0, w0);
            if (w2nd) sW[nxt][tid + 128] = make_float2(w1, w1);
        }
        __syncthreads();
    }

    // ---- store: 64-bit stores of adjacent-column pairs ----
#pragma unroll
    for (int co = 0; co < CO_TILE; co++) {
#pragma unroll
        for (int r2 = 0; r2 < 4; r2++) {
            int h = hb + r0 + r2;
            float* p = out + (((size_t)n * Cout + cog * CO_TILE + co) * HW + h) * HW + wb + c0;
            *reinterpret_cast<u64*>(p) = acc[co][r2];
        }
    }
}

extern "C" void kernel_launch(void* const* d_in, const int* in_sizes, int n_in,
                              void* d_out, int out_size)
{
    const float* x  = (const float*)d_in[0];
    const float* w1 = (const float*)d_in[1];
    const float* w2 = (const float*)d_in[2];
    const float* w3 = (const float*)d_in[3];
    float* out = (float*)d_out;

    float* buf1 = nullptr;
    float* buf2 = nullptr;
    cudaGetSymbolAddress((void**)&buf1, g_buf1);
    cudaGetSymbolAddress((void**)&buf2, g_buf2);

    dim3 block(128);
    dim3 grid1(128 / CO_TILE, 7 * 7, 16);
    conv3x3_pipe<64><<<grid1, block>>>(x, w1, buf1, 128);
    dim3 grid2(128 / CO_TILE, 7 * 7, 16);
    conv3x3_pipe<128><<<grid2, block>>>(buf1, w2, buf2, 128);
    dim3 grid3(64 / CO_TILE, 7 * 7, 16);
    conv3x3_pipe<128><<<grid3, block>>>(buf2, w3, out, 64);
}

// round 7
// speedup vs baseline: 2.3583x; 2.3583x over previous
#include <cuda_runtime.h>
#include <cstdint>

// ===========================================================================
// 3x conv3x3 chain via LEGACY tensor cores: mma.sync.m16n8k8 TF32 (sm_80 PTX,
// compiles for plain sm_103 target -- tcgen05 is blocked by the harness's
// PTX target). fp32 NCHW, N=16, H=W=224, 64 -> 128 -> 128 -> 64.
//
// Per CTA: D[MCTA co][112 pix] (one image row half). K = Cin*9 in chunks of 32
// (= one 3x3 tap x 32 input channels). Double-buffered smem filled with
// cp.async (overlaps MMA), operands pre-rounded to tf32-RN (no truncation
// bias, no hot-loop cvt). Inputs pre-padded to 226x256 planes -> branch-free.
// ===========================================================================

#define HW     224
#define PADH   226
#define PADW   256
#define PLANE  (PADH * PADW)
#define NIMG   16

// ---- scratch (device globals; allocations are banned) ----
__device__ float g_padX [NIMG *  64 * PLANE];
__device__ float g_padB1[NIMG * 128 * PLANE];
__device__ float g_padB2[NIMG * 128 * PLANE];
__device__ float g_wt1[18 * 128 * 36];   // prepacked [chunk][co][36] (pad 32->36)
__device__ float g_wt2[36 * 128 * 36];
__device__ float g_wt3[36 *  64 * 36];

// ---- smem layout (dynamic) ----
#define SA0 0
#define SA1 18432                    // 128*36*4
#define SB0 36864
#define SB1 52224                    // + 32*120*4
#define SMEM_TOTAL 67584

// ---- helpers ----
__device__ __forceinline__ uint32_t smem_u32(const void* p) {
    uint32_t a;
    asm("{ .reg .u64 t; cvta.to.shared.u64 t, %1; cvt.u32.u64 %0, t; }"
        : "=r"(a) : "l"(p));
    return a;
}
__device__ __forceinline__ void cp4(uint32_t dst, const float* src) {
    asm volatile("cp.async.ca.shared.global [%0], [%1], 4;"
                 :: "r"(dst), "l"(src) : "memory");
}
__device__ __forceinline__ void cp16(uint32_t dst, const float4* src) {
    asm volatile("cp.async.ca.shared.global [%0], [%1], 16;"
                 :: "r"(dst), "l"(src) : "memory");
}
#define CP_COMMIT() asm volatile("cp.async.commit_group;" ::: "memory")
#define CP_WAIT0()  asm volatile("cp.async.wait_group 0;"  ::: "memory")

__device__ __forceinline__ float tf32r(float x) {
    float y;
    asm("cvt.rna.tf32.f32 %0, %1;" : "=f"(y) : "f"(x));
    return y;
}

__device__ __forceinline__ void mma8(float* d, const uint32_t* a, const uint32_t* b) {
    asm volatile(
        "mma.sync.aligned.m16n8k8.row.col.f32.tf32.tf32.f32 "
        "{%0,%1,%2,%3}, {%4,%5,%6,%7}, {%8,%9}, {%0,%1,%2,%3};"
        : "+f"(d[0]), "+f"(d[1]), "+f"(d[2]), "+f"(d[3])
        : "r"(a[0]), "r"(a[1]), "r"(a[2]), "r"(a[3]), "r"(b[0]), "r"(b[1]));
}

// ===========================================================================
// main conv kernel
//   MT: m16-tiles per warp (2 -> MCTA=128, 1 -> MCTA=64)
// ===========================================================================
template <int CIN, int MT, bool CVT_OUT, bool OUT_PADDED>
__global__ __launch_bounds__(256, 2)
void conv_mma(const float* __restrict__ inPad,
              const float* __restrict__ wt,
              float* __restrict__ outp)
{
    constexpr int G    = CIN / 32;
    constexpr int NC   = 9 * G;
    constexpr int MCTA = MT * 64;
    constexpr int ASLOT = MCTA * 36 / 4;            // 16B slots per A chunk
    constexpr int AIT   = (ASLOT + 255) / 256;

    extern __shared__ __align__(16) char smem[];
    const uint32_t sb = smem_u32(smem);

    const int tid = threadIdx.x;
    const int wid = tid >> 5, lid = tid & 31;
    const int g   = lid >> 2, tg = lid & 3;
    const int half = blockIdx.x, h = blockIdx.y, n = blockIdx.z;
    const int p0  = half * 112;
    const int mb  = (wid & 3) * (MT * 16);          // warp co base
    const int nb  = (wid >> 2) * 56;                // warp pix base

    const float* src = inPad + (size_t)n * CIN * PLANE;

    float acc[MT][7][4];
#pragma unroll
    for (int m = 0; m < MT; m++)
#pragma unroll
        for (int nt = 0; nt < 7; nt++)
#pragma unroll
            for (int i = 0; i < 4; i++) acc[m][nt][i] = 0.0f;

    // B fill walker: slot = tid + 256*it over [32 ci][112 pix]
    const int ci_t = tid / 112;
    const int px_t = tid - ci_t * 112;

    auto fillA = [&](int s, uint32_t abuf) {
        const float4* w4 = (const float4*)(wt + (size_t)s * (MCTA * 36));
#pragma unroll
        for (int it = 0; it < AIT; it++) {
            int slot = it * 256 + tid;
            if (slot < ASLOT) cp16(abuf + slot * 16, w4 + slot);
        }
    };
    auto fillB = [&](int s, uint32_t bbuf) {
        int tap = s / G, gg = s - tap * G;
        int kh = tap / 3, kw = tap - kh * 3;
        const float* base = src + (size_t)gg * 32 * PLANE
                          + (h + kh) * PADW + 3 + kw + p0;
        int ci = ci_t, px = px_t;
#pragma unroll
        for (int it = 0; it < 14; it++) {
            cp4(bbuf + (uint32_t)(ci * 120 + px) * 4, base + (size_t)ci * PLANE + px);
            px += 32; ci += 2;
            if (px >= 112) { px -= 112; ci += 1; }
        }
    };

    // prologue: chunk 0
    fillA(0, sb + SA0);
    fillB(0, sb + SB0);
    CP_COMMIT(); CP_WAIT0();
    __syncthreads();

    for (int s = 0; s < NC; s++) {
        const int cur  = s & 1;
        const int aoff = cur ? SA1 : SA0;
        const int boff = cur ? SB1 : SB0;

        if (s + 1 < NC) {                 // prefetch next chunk (overlaps MMA)
            fillA(s + 1, sb + (cur ? SA0 : SA1));
            fillB(s + 1, sb + (cur ? SB0 : SB1));
            CP_COMMIT();
        }

        // compute chunk s: 4 k8-steps
#pragma unroll
        for (int ks = 0; ks < 4; ks++) {
            uint32_t a[MT][4];
#pragma unroll
            for (int m = 0; m < MT; m++) {
                int r0 = aoff + ((mb + m * 16 + g) * 36 + ks * 8 + tg) * 4;
                int r8 = r0 + 8 * 36 * 4;
                a[m][0] = *(const uint32_t*)(smem + r0);
                a[m][1] = *(const uint32_t*)(smem + r8);
                a[m][2] = *(const uint32_t*)(smem + r0 + 16);
                a[m][3] = *(const uint32_t*)(smem + r8 + 16);
            }
            uint32_t b[7][2];
#pragma unroll
            for (int nt = 0; nt < 7; nt++) {
                int c0 = boff + ((ks * 8 + tg) * 120 + nb + nt * 8 + g) * 4;
                b[nt][0] = *(const uint32_t*)(smem + c0);
                b[nt][1] = *(const uint32_t*)(smem + c0 + 4 * 120 * 4);
            }
#pragma unroll
            for (int m = 0; m < MT; m++)
#pragma unroll
                for (int nt = 0; nt < 7; nt++)
                    mma8(acc[m][nt], a[m], b[nt]);
        }

        CP_WAIT0();
        __syncthreads();
    }

    // ---- epilogue ----
#pragma unroll
    for (int m = 0; m < MT; m++) {
        const int r0 = mb + m * 16 + g;     // co of d0,d1 ; r0+8 for d2,d3
#pragma unroll
        for (int nt = 0; nt < 7; nt++) {
            int col = p0 + nb + nt * 8 + 2 * tg;
            float d0 = acc[m][nt][0], d1 = acc[m][nt][1];
            float d2 = acc[m][nt][2], d3 = acc[m][nt][3];
            if (CVT_OUT) { d0 = tf32r(d0); d1 = tf32r(d1); d2 = tf32r(d2); d3 = tf32r(d3); }
            if (OUT_PADDED) {
                float* pA = outp + ((size_t)(n * MCTA + r0)     * PADH + (h + 1)) * PADW + 4 + col;
                float* pB = outp + ((size_t)(n * MCTA + r0 + 8) * PADH + (h + 1)) * PADW + 4 + col;
                *(float2*)pA = make_float2(d0, d1);
                *(float2*)pB = make_float2(d2, d3);
            } else {
                float* pA = outp + ((size_t)(n * MCTA + r0)     * HW + h) * HW + col;
                float* pB = outp + ((size_t)(n * MCTA + r0 + 8) * HW + h) * HW + col;
                *(float2*)pA = make_float2(d0, d1);
                *(float2*)pB = make_float2(d2, d3);
            }
        }
    }
}

// ===========================================================================
// prep kernels
// ===========================================================================
__global__ void prep_borders()
{
    int plane = blockIdx.x;   // 0..5119
    float* base;
    if (plane < 1024)       base = g_padX  + (size_t)plane * PLANE;
    else if (plane < 3072)  base = g_padB1 + (size_t)(plane - 1024) * PLANE;
    else                    base = g_padB2 + (size_t)(plane - 3072) * PLANE;
    for (int e = threadIdx.x; e < 7680; e += blockDim.x) {
        int r, c;
        if (e < 256)      { r = 0;   c = e; }
        else if (e < 512) { r = 225; c = e - 256; }
        else {
            int e2 = e - 512;
            r = 1 + (e2 >> 5);
            int c5 = e2 & 31;
            c = (c5 < 4) ? c5 : 224 + c5;   // cols 0..3 and 228..255
        }
        base[r * PADW + c] = 0.0f;
    }
}

__global__ void prep_pad_x(const float* __restrict__ x)
{
    int plane = blockIdx.y;
    int idx   = blockIdx.x * 256 + threadIdx.x;
    if (idx >= HW * HW) return;
    int hh = idx / HW, ww = idx - hh * HW;
    g_padX[((size_t)plane * PADH + hh + 1) * PADW + 4 + ww] =
        tf32r(x[(size_t)plane * HW * HW + idx]);
}

template <int CIN, int MCTA>
__global__ void prep_wt(const float* __restrict__ w, float* __restrict__ wt)
{
    constexpr int G = CIN / 32, NC = 9 * G;
    size_t total = (size_t)NC * MCTA * 36;
    for (size_t i = (size_t)blockIdx.x * blockDim.x + threadIdx.x; i < total;
         i += (size_t)gridDim.x * blockDim.x) {
        int c36 = (int)(i % 36);
        size_t t = i / 36;
        int co = (int)(t % MCTA);
        int s  = (int)(t / MCTA);
        int tap = s / G, gg = s - tap * G;
        int kh = tap / 3, kw = tap - kh * 3;
        float v = 0.0f;
        if (c36 < 32) {
            int ci = gg * 32 + c36;
            v = tf32r(w[((co * CIN + ci) * 3 + kh) * 3 + kw]);
        }
        wt[i] = v;
    }
}

// ===========================================================================
extern "C" void kernel_launch(void* const* d_in, const int* in_sizes, int n_in,
                              void* d_out, int out_size)
{
    const float* x  = (const float*)d_in[0];
    const float* w1 = (const float*)d_in[1];
    const float* w2 = (const float*)d_in[2];
    const float* w3 = (const float*)d_in[3];
    float* out = (float*)d_out;

    float *padX, *padB1, *padB2, *wt1, *wt2, *wt3;
    cudaGetSymbolAddress((void**)&padX,  g_padX);
    cudaGetSymbolAddress((void**)&padB1, g_padB1);
    cudaGetSymbolAddress((void**)&padB2, g_padB2);
    cudaGetSymbolAddress((void**)&wt1, g_wt1);
    cudaGetSymbolAddress((void**)&wt2, g_wt2);
    cudaGetSymbolAddress((void**)&wt3, g_wt3);

    cudaFuncSetAttribute(conv_mma< 64, 2, true,  true >,
                         cudaFuncAttributeMaxDynamicSharedMemorySize, SMEM_TOTAL);
    cudaFuncSetAttribute(conv_mma<128, 2, true,  true >,
                         cudaFuncAttributeMaxDynamicSharedMemorySize, SMEM_TOTAL);
    cudaFuncSetAttribute(conv_mma<128, 1, false, false>,
                         cudaFuncAttributeMaxDynamicSharedMemorySize, SMEM_TOTAL);

    // prep
    prep_borders<<<5120, 256>>>();
    dim3 gpad((HW * HW + 255) / 256, NIMG * 64);
    prep_pad_x<<<gpad, 256>>>(x);
    prep_wt< 64, 128><<<324, 256>>>(w1, wt1);
    prep_wt<128, 128><<<648, 256>>>(w2, wt2);
    prep_wt<128,  64><<<324, 256>>>(w3, wt3);

    // convs: one CTA per (half-row, row, image)
    dim3 grid(2, HW, NIMG), block(256);
    conv_mma< 64, 2, true,  true ><<<grid, block, SMEM_TOTAL>>>(padX,  wt1, padB1);
    conv_mma<128, 2, true,  true ><<<grid, block, SMEM_TOTAL>>>(padB1, wt2, padB2);
    conv_mma<128, 1, false, false><<<grid, block, SMEM_TOTAL>>>(padB2, wt3, out);
}

// round 8
// speedup vs baseline: 4.9295x; 2.0903x over previous
#include <cuda_runtime.h>
#include <cuda_fp16.h>
#include <cstdint>

// ===========================================================================
// 3x conv3x3 chain via mma.sync.m16n8k16 FP16 (fp32 accum) -- same 11-bit
// significand as tf32 but 2x K per HMMA. fp32 NCHW in/out; intermediates are
// NHWC half padded planes (ci fastest) so B-tile fill is contiguous cp.async.
// N=16, H=W=224, 64 -> 128 -> 128 -> 64.
//
// Per CTA: D[MCTA co][112 pix] (one image row half). K = Cin*9 in chunks of
// 32 (one 3x3 tap x 32 ci), 2 k16-steps per chunk. Double-buffered smem,
// cp.async overlapping MMA. A/B smem rows padded to 40 halfs -> conflict-free
// fragment loads.
// ===========================================================================

#define HW     224
#define PADH   226
#define PADW   256
#define NIMG   16

// ---- scratch (device globals; allocations banned) ----
__device__ __half g_padX [NIMG * PADH * PADW *  64];   // NHWC half, padded
__device__ __half g_padB1[NIMG * PADH * PADW * 128];
__device__ __half g_padB2[NIMG * PADH * PADW * 128];
__device__ __half g_wt1[18 * 128 * 40];                // [chunk][co][40]
__device__ __half g_wt2[36 * 128 * 40];
__device__ __half g_wt3[36 *  64 * 40];

// ---- helpers ----
__device__ __forceinline__ uint32_t smem_u32(const void* p) {
    uint32_t a;
    asm("{ .reg .u64 t; cvta.to.shared.u64 t, %1; cvt.u32.u64 %0, t; }"
        : "=r"(a) : "l"(p));
    return a;
}
__device__ __forceinline__ void cp16(uint32_t dst, const void* src) {
    asm volatile("cp.async.ca.shared.global [%0], [%1], 16;"
                 :: "r"(dst), "l"(src) : "memory");
}
#define CP_COMMIT() asm volatile("cp.async.commit_group;" ::: "memory")
#define CP_WAIT0()  asm volatile("cp.async.wait_group 0;"  ::: "memory")

__device__ __forceinline__ void mma16(float* d, const uint32_t* a, const uint32_t* b) {
    asm volatile(
        "mma.sync.aligned.m16n8k16.row.col.f32.f16.f16.f32 "
        "{%0,%1,%2,%3}, {%4,%5,%6,%7}, {%8,%9}, {%0,%1,%2,%3};"
        : "+f"(d[0]), "+f"(d[1]), "+f"(d[2]), "+f"(d[3])
        : "r"(a[0]), "r"(a[1]), "r"(a[2]), "r"(a[3]), "r"(b[0]), "r"(b[1]));
}

// ===========================================================================
// main conv kernel. MT=2 -> MCTA=128 co, MT=1 -> 64.
// OUT_HALF: write NHWC half padded plane; else fp32 NCHW (final output).
// ===========================================================================
template <int CIN, int MT, bool OUT_HALF>
__global__ __launch_bounds__(256, 2)
void conv_mma16(const __half* __restrict__ inPad,
                const __half* __restrict__ wt,
                void* __restrict__ outp)
{
    constexpr int G     = CIN / 32;
    constexpr int NC    = 9 * G;
    constexpr int MCTA  = MT * 64;
    constexpr int ABYTE = MCTA * 80;          // MCTA rows x 40 halfs
    constexpr int BBYTE = 112 * 80;           // 112 pix rows x 40 halfs
    constexpr int SA0 = 0, SA1 = ABYTE, SB0 = 2 * ABYTE, SB1 = 2 * ABYTE + BBYTE;
    constexpr int ASLOT = ABYTE / 16;         // 16B slots per A chunk
    constexpr int BSLOT = 448;                // 112 pix * 4 (64B of ci data each)

    extern __shared__ __align__(16) char smem[];
    const uint32_t sb = smem_u32(smem);

    const int tid = threadIdx.x;
    const int wid = tid >> 5, lid = tid & 31;
    const int g   = lid >> 2, tg = lid & 3;
    const int half_ = blockIdx.x, h = blockIdx.y, n = blockIdx.z;
    const int p0  = half_ * 112;
    const int mb  = (wid & 3) * (MT * 16);
    const int nb  = (wid >> 2) * 56;

    const __half* src = inPad + (size_t)n * PADH * PADW * CIN;

    float acc[MT][7][4];
#pragma unroll
    for (int m = 0; m < MT; m++)
#pragma unroll
        for (int nt = 0; nt < 7; nt++)
#pragma unroll
            for (int i = 0; i < 4; i++) acc[m][nt][i] = 0.0f;

    auto fillA = [&](int s, uint32_t abuf) {
        const char* w16 = (const char*)(wt + (size_t)s * (MCTA * 40));
#pragma unroll
        for (int it = 0; it * 256 < ASLOT; it++) {
            int slot = it * 256 + tid;
            if ((ASLOT % 256 == 0) || slot < ASLOT)
                cp16(abuf + slot * 16, w16 + slot * 16);
        }
    };
    auto fillB = [&](int s, uint32_t bbuf) {
        int tap = s / G, gg = s - tap * G;
        int kh = tap / 3, kw = tap - kh * 3;
        const __half* base = src + ((size_t)(h + kh) * PADW + 3 + kw + p0) * CIN + gg * 32;
#pragma unroll
        for (int it = 0; it < 2; it++) {
            int slot = it * 256 + tid;
            if (it == 0 || slot < BSLOT) {
                int pix = slot >> 2, q = slot & 3;
                cp16(bbuf + (uint32_t)(pix * 80 + q * 16),
                     base + (size_t)pix * CIN + q * 8);
            }
        }
    };

    // prologue
    fillA(0, sb + SA0);
    fillB(0, sb + SB0);
    CP_COMMIT(); CP_WAIT0();
    __syncthreads();

    for (int s = 0; s < NC; s++) {
        const int cur  = s & 1;
        const int aoff = cur ? SA1 : SA0;
        const int boff = cur ? SB1 : SB0;

        if (s + 1 < NC) {
            fillA(s + 1, sb + (cur ? SA0 : SA1));
            fillB(s + 1, sb + (cur ? SB0 : SB1));
            CP_COMMIT();
        }

        // 2 k16 steps
#pragma unroll
        for (int ks = 0; ks < 2; ks++) {
            uint32_t a[MT][4];
#pragma unroll
            for (int m = 0; m < MT; m++) {
                int base = aoff + (mb + m * 16 + g) * 80 + ks * 32 + tg * 4;
                a[m][0] = *(const uint32_t*)(smem + base);
                a[m][1] = *(const uint32_t*)(smem + base + 640);   // +8 rows
                a[m][2] = *(const uint32_t*)(smem + base + 16);    // k+8
                a[m][3] = *(const uint32_t*)(smem + base + 656);
            }
            uint32_t b[7][2];
#pragma unroll
            for (int nt = 0; nt < 7; nt++) {
                int base = boff + (nb + nt * 8 + g) * 80 + ks * 32 + tg * 4;
                b[nt][0] = *(const uint32_t*)(smem + base);
                b[nt][1] = *(const uint32_t*)(smem + base + 16);
            }
#pragma unroll
            for (int m = 0; m < MT; m++)
#pragma unroll
                for (int nt = 0; nt < 7; nt++)
                    mma16(acc[m][nt], a[m], b[nt]);
        }

        CP_WAIT0();
        __syncthreads();
    }

    // ---- epilogue ----
    if (OUT_HALF) {
        // transpose through smem (pitch 136 halfs), then coalesced NHWC stores
        __half* sOut = (__half*)smem;
#pragma unroll
        for (int m = 0; m < MT; m++) {
            int co = mb + m * 16 + g;
#pragma unroll
            for (int nt = 0; nt < 7; nt++) {
                int pix = nb + nt * 8 + 2 * tg;
                sOut[(size_t)pix * 136 + co]           = __float2half_rn(acc[m][nt][0]);
                sOut[(size_t)(pix + 1) * 136 + co]     = __float2half_rn(acc[m][nt][1]);
                sOut[(size_t)pix * 136 + co + 8]       = __float2half_rn(acc[m][nt][2]);
                sOut[(size_t)(pix + 1) * 136 + co + 8] = __float2half_rn(acc[m][nt][3]);
            }
        }
        __syncthreads();
        __half* base = (__half*)outp
            + (((size_t)n * PADH + h + 1) * PADW + 4 + p0) * MCTA;
        for (int s = tid; s < 112 * MCTA / 8; s += 256) {
            int pix = s / (MCTA / 8), q = s - pix * (MCTA / 8);
            *(uint4*)(base + (size_t)pix * MCTA + q * 8) =
                *(const uint4*)(sOut + (size_t)pix * 136 + q * 8);
        }
    } else {
        float* fo = (float*)outp;
#pragma unroll
        for (int m = 0; m < MT; m++) {
            int r0 = mb + m * 16 + g;
#pragma unroll
            for (int nt = 0; nt < 7; nt++) {
                int col = p0 + nb + nt * 8 + 2 * tg;
                float* pA = fo + ((size_t)(n * MCTA + r0)     * HW + h) * HW + col;
                float* pB = fo + ((size_t)(n * MCTA + r0 + 8) * HW + h) * HW + col;
                *(float2*)pA = make_float2(acc[m][nt][0], acc[m][nt][1]);
                *(float2*)pB = make_float2(acc[m][nt][2], acc[m][nt][3]);
            }
        }
    }
}

// ===========================================================================
// prep kernels
// ===========================================================================
// zero borders of all three NHWC padded buffers
__global__ void prep_borders()
{
    int bx = blockIdx.x;                 // 0 .. 3*16*226-1
    int buf = bx / (NIMG * PADH);
    int r   = bx - buf * (NIMG * PADH);
    int n   = r / PADH, hh = r - n * PADH;
    int cin = (buf == 0) ? 64 : 128;
    __half* base = (buf == 0) ? g_padX : (buf == 1) ? g_padB1 : g_padB2;
    __half* row = base + ((size_t)n * PADH + hh) * PADW * cin;
    const uint4 z = make_uint4(0, 0, 0, 0);
    if (hh == 0 || hh == PADH - 1) {
        int slots = PADW * cin / 8;
        for (int s = threadIdx.x; s < slots; s += blockDim.x)
            *(uint4*)(row + (size_t)s * 8) = z;
    } else {
        int slots = 4 * cin / 8;         // cols 0..3 and 228..255 (28 cols)
        for (int s = threadIdx.x; s < slots; s += blockDim.x)
            *(uint4*)(row + (size_t)s * 8) = z;
        int slots2 = 28 * cin / 8;
        __half* row2 = row + (size_t)228 * cin;
        for (int s = threadIdx.x; s < slots2; s += blockDim.x)
            *(uint4*)(row2 + (size_t)s * 8) = z;
    }
}

// NCHW f32 -> NHWC half padded (conv1 input). block = (h, n)
__global__ void prep_pad_x(const float* __restrict__ x)
{
    __shared__ __half sT[224 * 72];
    int h = blockIdx.x, n = blockIdx.y;
    for (int idx = threadIdx.x; idx < 64 * 224; idx += 256) {
        int ci = idx / 224, w = idx - ci * 224;
        float v = x[(((size_t)n * 64 + ci) * HW + h) * HW + w];
        sT[w * 72 + ci] = __float2half_rn(v);
    }
    __syncthreads();
    __half* base = g_padX + (((size_t)n * PADH + h + 1) * PADW + 4) * 64;
    for (int s = threadIdx.x; s < 224 * 8; s += 256) {
        int w = s >> 3, q = s & 7;
        *(uint4*)(base + (size_t)w * 64 + q * 8) = *(const uint4*)(sT + w * 72 + q * 8);
    }
}

template <int CIN, int MCTA>
__global__ void prep_wt(const float* __restrict__ w, __half* __restrict__ wt)
{
    constexpr int G = CIN / 32, NC = 9 * G;
    size_t total = (size_t)NC * MCTA * 40;
    for (size_t i = (size_t)blockIdx.x * blockDim.x + threadIdx.x; i < total;
         i += (size_t)gridDim.x * blockDim.x) {
        int c40 = (int)(i % 40);
        size_t t = i / 40;
        int co = (int)(t % MCTA);
        int s  = (int)(t / MCTA);
        int tap = s / G, gg = s - tap * G;
        int kh = tap / 3, kw = tap - kh * 3;
        float v = 0.0f;
        if (c40 < 32) {
            int ci = gg * 32 + c40;
            v = w[((co * CIN + ci) * 3 + kh) * 3 + kw];
        }
        wt[i] = __float2half_rn(v);
    }
}

// ===========================================================================
extern "C" void kernel_launch(void* const* d_in, const int* in_sizes, int n_in,
                              void* d_out, int out_size)
{
    const float* x  = (const float*)d_in[0];
    const float* w1 = (const float*)d_in[1];
    const float* w2 = (const float*)d_in[2];
    const float* w3 = (const float*)d_in[3];
    float* out = (float*)d_out;

    __half *padX, *padB1, *padB2, *wt1, *wt2, *wt3;
    cudaGetSymbolAddress((void**)&padX,  g_padX);
    cudaGetSymbolAddress((void**)&padB1, g_padB1);
    cudaGetSymbolAddress((void**)&padB2, g_padB2);
    cudaGetSymbolAddress((void**)&wt1, g_wt1);
    cudaGetSymbolAddress((void**)&wt2, g_wt2);
    cudaGetSymbolAddress((void**)&wt3, g_wt3);

    constexpr int SM_MT2 = 2 * (128 * 80) + 2 * (112 * 80);   // 38400
    constexpr int SM_MT1 = 2 * ( 64 * 80) + 2 * (112 * 80);   // 28160
    cudaFuncSetAttribute(conv_mma16< 64, 2, true >,
                         cudaFuncAttributeMaxDynamicSharedMemorySize, SM_MT2);
    cudaFuncSetAttribute(conv_mma16<128, 2, true >,
                         cudaFuncAttributeMaxDynamicSharedMemorySize, SM_MT2);
    cudaFuncSetAttribute(conv_mma16<128, 1, false>,
                         cudaFuncAttributeMaxDynamicSharedMemorySize, SM_MT1);

    // prep
    prep_borders<<<3 * NIMG * PADH, 256>>>();
    dim3 gpad(HW, NIMG);
    prep_pad_x<<<gpad, 256>>>(x);
    prep_wt< 64, 128><<<360, 256>>>(w1, wt1);
    prep_wt<128, 128><<<720, 256>>>(w2, wt2);
    prep_wt<128,  64><<<360, 256>>>(w3, wt3);

    // convs
    dim3 grid(2, HW, NIMG), block(256);
    conv_mma16< 64, 2, true ><<<grid, block, SM_MT2>>>(padX,  wt1, padB1);
    conv_mma16<128, 2, true ><<<grid, block, SM_MT2>>>(padB1, wt2, padB2);
    conv_mma16<128, 1, false><<<grid, block, SM_MT1>>>(padB2, wt3, out);
}

// round 9
// speedup vs baseline: 5.8290x; 1.1825x over previous
#include <cuda_runtime.h>
#include <cuda_fp16.h>
#include <cstdint>

// ===========================================================================
// 3x conv3x3 chain via mma.sync.m16n8k16 FP16 (fp32 accum), NHWC half
// intermediates. Round 9: ldmatrix fragment loads (44 LDS.32 -> 12 ldmatrix
// per warp-chunk) + 3-stage cp.async pipeline (fills get ~2 chunks of slack).
// N=16, H=W=224, 64 -> 128 -> 128 -> 64, fp32 NCHW in/out.
// ===========================================================================

#define HW     224
#define PADH   226
#define PADW   256
#define NIMG   16

__device__ __half g_padX [NIMG * PADH * PADW *  64];
__device__ __half g_padB1[NIMG * PADH * PADW * 128];
__device__ __half g_padB2[NIMG * PADH * PADW * 128];
__device__ __half g_wt1[18 * 128 * 40];
__device__ __half g_wt2[36 * 128 * 40];
__device__ __half g_wt3[36 *  64 * 40];

__device__ __forceinline__ uint32_t smem_u32(const void* p) {
    uint32_t a;
    asm("{ .reg .u64 t; cvta.to.shared.u64 t, %1; cvt.u32.u64 %0, t; }"
        : "=r"(a) : "l"(p));
    return a;
}
__device__ __forceinline__ void cp16(uint32_t dst, const void* src) {
    asm volatile("cp.async.ca.shared.global [%0], [%1], 16;"
                 :: "r"(dst), "l"(src) : "memory");
}
#define CP_COMMIT() asm volatile("cp.async.commit_group;" ::: "memory")
#define CP_WAIT0()  asm volatile("cp.async.wait_group 0;"  ::: "memory")
#define CP_WAIT1()  asm volatile("cp.async.wait_group 1;"  ::: "memory")

__device__ __forceinline__ void ldm4(uint32_t* r, uint32_t addr) {
    asm volatile("ldmatrix.sync.aligned.m8n8.x4.shared.b16 {%0,%1,%2,%3}, [%4];"
                 : "=r"(r[0]), "=r"(r[1]), "=r"(r[2]), "=r"(r[3]) : "r"(addr));
}
__device__ __forceinline__ void ldm2(uint32_t* r, uint32_t addr) {
    asm volatile("ldmatrix.sync.aligned.m8n8.x2.shared.b16 {%0,%1}, [%2];"
                 : "=r"(r[0]), "=r"(r[1]) : "r"(addr));
}
__device__ __forceinline__ void mma16(float* d, const uint32_t* a, const uint32_t* b) {
    asm volatile(
        "mma.sync.aligned.m16n8k16.row.col.f32.f16.f16.f32 "
        "{%0,%1,%2,%3}, {%4,%5,%6,%7}, {%8,%9}, {%0,%1,%2,%3};"
        : "+f"(d[0]), "+f"(d[1]), "+f"(d[2]), "+f"(d[3])
        : "r"(a[0]), "r"(a[1]), "r"(a[2]), "r"(a[3]), "r"(b[0]), "r"(b[1]));
}

// ===========================================================================
template <int CIN, int MT, bool OUT_HALF>
__global__ __launch_bounds__(256, 2)
void conv_mma16(const __half* __restrict__ inPad,
                const __half* __restrict__ wt,
                void* __restrict__ outp)
{
    constexpr int G     = CIN / 32;
    constexpr int NC    = 9 * G;
    constexpr int MCTA  = MT * 64;
    constexpr int ABYTE = MCTA * 80;
    constexpr int BBYTE = 112 * 80;
    constexpr int STAGE = ABYTE + BBYTE;      // A then B per stage
    constexpr int ASLOT = ABYTE / 16;
    constexpr int BSLOT = 448;

    extern __shared__ __align__(16) char smem[];
    const uint32_t sb = smem_u32(smem);

    const int tid = threadIdx.x;
    const int wid = tid >> 5, lid = tid & 31;
    const int g   = lid >> 2, tg = lid & 3;
    const int tix = lid & 7, quad = lid >> 3;
    const int half_ = blockIdx.x, h = blockIdx.y, n = blockIdx.z;
    const int p0  = half_ * 112;
    const int mb  = (wid & 3) * (MT * 16);
    const int nb  = (wid >> 2) * 56;

    // ldmatrix per-thread address components (byte offsets within a stage)
    // A: r0=rows+0/k0, r1=rows+8/k0, r2=rows+0/k+8, r3=rows+8/k+8
    const uint32_t aAddr0 = (uint32_t)((mb + (quad & 1) * 8 + tix) * 80 + (quad >> 1) * 16);
    // B: r0=rows+0/k0, r1=rows+0/k+8, r2=rows+8/k0, r3=rows+8/k+8
    const uint32_t bAddr0 = (uint32_t)(ABYTE + (nb + (quad >> 1) * 8 + tix) * 80 + (quad & 1) * 16);

    const __half* src = inPad + (size_t)n * PADH * PADW * CIN;

    float acc[MT][7][4];
#pragma unroll
    for (int m = 0; m < MT; m++)
#pragma unroll
        for (int nt = 0; nt < 7; nt++)
#pragma unroll
            for (int i = 0; i < 4; i++) acc[m][nt][i] = 0.0f;

    auto fillA = [&](int s, uint32_t abuf) {
        const char* w16 = (const char*)(wt + (size_t)s * (MCTA * 40));
#pragma unroll
        for (int it = 0; it * 256 < ASLOT; it++) {
            int slot = it * 256 + tid;
            if ((ASLOT % 256 == 0) || slot < ASLOT)
                cp16(abuf + slot * 16, w16 + slot * 16);
        }
    };
    auto fillB = [&](int s, uint32_t bbuf) {
        int tap = s / G, gg = s - tap * G;
        int kh = tap / 3, kw = tap - kh * 3;
        const __half* base = src + ((size_t)(h + kh) * PADW + 3 + kw + p0) * CIN + gg * 32;
#pragma unroll
        for (int it = 0; it < 2; it++) {
            int slot = it * 256 + tid;
            if (it == 0 || slot < BSLOT) {
                int pix = slot >> 2, q = slot & 3;
                cp16(bbuf + (uint32_t)(pix * 80 + q * 16),
                     base + (size_t)pix * CIN + q * 8);
            }
        }
    };
    auto fillStage = [&](int s) {
        uint32_t st = sb + (s % 3) * STAGE;
        fillA(s, st);
        fillB(s, st + ABYTE);
        CP_COMMIT();
    };

    // prologue: stages 0 and 1 in flight
    fillStage(0);
    fillStage(1);

    for (int s = 0; s < NC; s++) {
        if (s >= NC - 1) { CP_WAIT0(); } else { CP_WAIT1(); }
        __syncthreads();
        if (s + 2 < NC) fillStage(s + 2);

        const uint32_t st = sb + (s % 3) * STAGE;
        const uint32_t aB = st + aAddr0;
        const uint32_t bB = st + bAddr0;

#pragma unroll
        for (int ks = 0; ks < 2; ks++) {
            uint32_t a[MT][4];
#pragma unroll
            for (int m = 0; m < MT; m++)
                ldm4(a[m], aB + m * 1280 + ks * 32);
            uint32_t b[7][2];
#pragma unroll
            for (int pr = 0; pr < 3; pr++) {
                uint32_t r4[4];
                ldm4(r4, bB + pr * 1280 + ks * 32);
                b[2 * pr][0] = r4[0]; b[2 * pr][1] = r4[1];
                b[2 * pr + 1][0] = r4[2]; b[2 * pr + 1][1] = r4[3];
            }
            ldm2(b[6], bB + 3 * 1280 + ks * 32);
#pragma unroll
            for (int m = 0; m < MT; m++)
#pragma unroll
                for (int nt = 0; nt < 7; nt++)
                    mma16(acc[m][nt], a[m], b[nt]);
        }
        __syncthreads();   // all warps done reading stage s before its buffer refills
    }

    // ---- epilogue ----
    if (OUT_HALF) {
        __half* sOut = (__half*)smem;
#pragma unroll
        for (int m = 0; m < MT; m++) {
            int co = mb + m * 16 + g;
#pragma unroll
            for (int nt = 0; nt < 7; nt++) {
                int pix = nb + nt * 8 + 2 * tg;
                sOut[(size_t)pix * 136 + co]           = __float2half_rn(acc[m][nt][0]);
                sOut[(size_t)(pix + 1) * 136 + co]     = __float2half_rn(acc[m][nt][1]);
                sOut[(size_t)pix * 136 + co + 8]       = __float2half_rn(acc[m][nt][2]);
                sOut[(size_t)(pix + 1) * 136 + co + 8] = __float2half_rn(acc[m][nt][3]);
            }
        }
        __syncthreads();
        __half* base = (__half*)outp
            + (((size_t)n * PADH + h + 1) * PADW + 4 + p0) * MCTA;
        for (int s = tid; s < 112 * MCTA / 8; s += 256) {
            int pix = s / (MCTA / 8), q = s - pix * (MCTA / 8);
            *(uint4*)(base + (size_t)pix * MCTA + q * 8) =
                *(const uint4*)(sOut + (size_t)pix * 136 + q * 8);
        }
    } else {
        float* fo = (float*)outp;
#pragma unroll
        for (int m = 0; m < MT; m++) {
            int r0 = mb + m * 16 + g;
#pragma unroll
            for (int nt = 0; nt < 7; nt++) {
                int col = p0 + nb + nt * 8 + 2 * tg;
                float* pA = fo + ((size_t)(n * MCTA + r0)     * HW + h) * HW + col;
                float* pB = fo + ((size_t)(n * MCTA + r0 + 8) * HW + h) * HW + col;
                *(float2*)pA = make_float2(acc[m][nt][0], acc[m][nt][1]);
                *(float2*)pB = make_float2(acc[m][nt][2], acc[m][nt][3]);
            }
        }
    }
}

// ===========================================================================
// prep kernels
// ===========================================================================
__global__ void prep_borders()
{
    int bx = blockIdx.x;
    int buf = bx / (NIMG * PADH);
    int r   = bx - buf * (NIMG * PADH);
    int n   = r / PADH, hh = r - n * PADH;
    int cin = (buf == 0) ? 64 : 128;
    __half* base = (buf == 0) ? g_padX : (buf == 1) ? g_padB1 : g_padB2;
    __half* row = base + ((size_t)n * PADH + hh) * PADW * cin;
    const uint4 z = make_uint4(0, 0, 0, 0);
    if (hh == 0 || hh == PADH - 1) {
        int slots = PADW * cin / 8;
        for (int s = threadIdx.x; s < slots; s += blockDim.x)
            *(uint4*)(row + (size_t)s * 8) = z;
    } else {
        int slots = 4 * cin / 8;
        for (int s = threadIdx.x; s < slots; s += blockDim.x)
            *(uint4*)(row + (size_t)s * 8) = z;
        int slots2 = 28 * cin / 8;
        __half* row2 = row + (size_t)228 * cin;
        for (int s = threadIdx.x; s < slots2; s += blockDim.x)
            *(uint4*)(row2 + (size_t)s * 8) = z;
    }
}

__global__ void prep_pad_x(const float* __restrict__ x)
{
    __shared__ __half sT[224 * 72];
    int h = blockIdx.x, n = blockIdx.y;
    for (int idx = threadIdx.x; idx < 64 * 224; idx += 256) {
        int ci = idx / 224, w = idx - ci * 224;
        float v = x[(((size_t)n * 64 + ci) * HW + h) * HW + w];
        sT[w * 72 + ci] = __float2half_rn(v);
    }
    __syncthreads();
    __half* base = g_padX + (((size_t)n * PADH + h + 1) * PADW + 4) * 64;
    for (int s = threadIdx.x; s < 224 * 8; s += 256) {
        int w = s >> 3, q = s & 7;
        *(uint4*)(base + (size_t)w * 64 + q * 8) = *(const uint4*)(sT + w * 72 + q * 8);
    }
}

template <int CIN, int MCTA>
__global__ void prep_wt(const float* __restrict__ w, __half* __restrict__ wt)
{
    constexpr int G = CIN / 32, NC = 9 * G;
    size_t total = (size_t)NC * MCTA * 40;
    for (size_t i = (size_t)blockIdx.x * blockDim.x + threadIdx.x; i < total;
         i += (size_t)gridDim.x * blockDim.x) {
        int c40 = (int)(i % 40);
        size_t t = i / 40;
        int co = (int)(t % MCTA);
        int s  = (int)(t / MCTA);
        int tap = s / G, gg = s - tap * G;
        int kh = tap / 3, kw = tap - kh * 3;
        float v = 0.0f;
        if (c40 < 32) {
            int ci = gg * 32 + c40;
            v = w[((co * CIN + ci) * 3 + kh) * 3 + kw];
        }
        wt[i] = __float2half_rn(v);
    }
}

// ===========================================================================
extern "C" void kernel_launch(void* const* d_in, const int* in_sizes, int n_in,
                              void* d_out, int out_size)
{
    const float* x  = (const float*)d_in[0];
    const float* w1 = (const float*)d_in[1];
    const float* w2 = (const float*)d_in[2];
    const float* w3 = (const float*)d_in[3];
    float* out = (float*)d_out;

    __half *padX, *padB1, *padB2, *wt1, *wt2, *wt3;
    cudaGetSymbolAddress((void**)&padX,  g_padX);
    cudaGetSymbolAddress((void**)&padB1, g_padB1);
    cudaGetSymbolAddress((void**)&padB2, g_padB2);
    cudaGetSymbolAddress((void**)&wt1, g_wt1);
    cudaGetSymbolAddress((void**)&wt2, g_wt2);
    cudaGetSymbolAddress((void**)&wt3, g_wt3);

    constexpr int SM_MT2 = 3 * (128 * 80 + 112 * 80);   // 57600
    constexpr int SM_MT1 = 3 * ( 64 * 80 + 112 * 80);   // 42240
    cudaFuncSetAttribute(conv_mma16< 64, 2, true >,
                         cudaFuncAttributeMaxDynamicSharedMemorySize, SM_MT2);
    cudaFuncSetAttribute(conv_mma16<128, 2, true >,
                         cudaFuncAttributeMaxDynamicSharedMemorySize, SM_MT2);
    cudaFuncSetAttribute(conv_mma16<128, 1, false>,
                         cudaFuncAttributeMaxDynamicSharedMemorySize, SM_MT1);

    prep_borders<<<3 * NIMG * PADH, 256>>>();
    dim3 gpad(HW, NIMG);
    prep_pad_x<<<gpad, 256>>>(x);
    prep_wt< 64, 128><<<360, 256>>>(w1, wt1);
    prep_wt<128, 128><<<720, 256>>>(w2, wt2);
    prep_wt<128,  64><<<360, 256>>>(w3, wt3);

    dim3 grid(2, HW, NIMG), block(256);
    conv_mma16< 64, 2, true ><<<grid, block, SM_MT2>>>(padX,  wt1, padB1);
    conv_mma16<128, 2, true ><<<grid, block, SM_MT2>>>(padB1, wt2, padB2);
    conv_mma16<128, 1, false><<<grid, block, SM_MT1>>>(padB2, wt3, out);
}